// round 12
// baseline (speedup 1.0000x reference)
#include <cuda_runtime.h>
#include <cuda_fp16.h>

#define NN 100000
#define NE 1600000
#define FIN 20
#define HID 64
#define NG 2000
#define BKT 64   // padded bucket slots per node (P(deg>=64) ~ 1e-20)

// ---------------- scratch ----------------------------------------------------
__device__ int    g_cnt[NN];           // per-node real degree (excl self-loop)
__device__ float  g_dinv[NN];
__device__ int    g_esrc[NN * BKT];    // padded buckets: src ids for dst=node
__device__ __half g_x16[NN * 32];      // dinv*x in fp16, row stride 32 (20 valid)
__device__ __half g_h16[NN * HID];     // dinv*relu(h1) (fp16)
__device__ __half g_h16b[NN * HID];    // dinv*relu(h2) (fp16) — ping-pong
__device__ __half g_wt1[HID * 32];     // W1^T fp16, [n][k], k padded 20->32
__device__ __half g_wt2[HID * HID];    // W2^T fp16, [n][k]
__device__ __half g_wt3[HID * HID];    // W3^T fp16, [n][k]
__device__ float  g_sums[NG * HID];
__device__ float  g_cnts[NG];
__device__ int    g_i64;

// ---------------- helpers -----------------------------------------------------
__device__ __forceinline__ int ld_idx(const void* p, long long i, int is64) {
    return ((const int*)p)[is64 ? 2 * i : i];
}

__device__ __forceinline__ void red_add_v4(float* addr, float4 v) {
    asm volatile("red.global.add.v4.f32 [%0], {%1,%2,%3,%4};"
                 :: "l"(addr), "f"(v.x), "f"(v.y), "f"(v.z), "f"(v.w)
                 : "memory");
}

__device__ __forceinline__ void add4_h(const uint2 u, float* acc) {
    float2 f0 = __half22float2(*(const __half2*)&u.x);
    float2 f1 = __half22float2(*(const __half2*)&u.y);
    acc[0] += f0.x; acc[1] += f0.y;
    acc[2] += f1.x; acc[3] += f1.y;
}

__device__ __forceinline__ uint2 hadd2x2(uint2 a, uint2 b) {
    __half2 lo = __hadd2(*(const __half2*)&a.x, *(const __half2*)&b.x);
    __half2 hi = __hadd2(*(const __half2*)&a.y, *(const __half2*)&b.y);
    uint2 r; r.x = *(unsigned*)&lo; r.y = *(unsigned*)&hi; return r;
}

__device__ __forceinline__ unsigned haddu(unsigned a, unsigned b) {
    __half2 r = __hadd2(*(const __half2*)&a, *(const __half2*)&b);
    return *(unsigned*)&r;
}

__device__ __forceinline__ void mma16816(float& d0, float& d1, float& d2, float& d3,
                                         unsigned a0, unsigned a1, unsigned a2, unsigned a3,
                                         unsigned b0, unsigned b1) {
    asm volatile(
        "mma.sync.aligned.m16n8k16.row.col.f32.f16.f16.f32 "
        "{%0,%1,%2,%3}, {%4,%5,%6,%7}, {%8,%9}, {%0,%1,%2,%3};"
        : "+f"(d0), "+f"(d1), "+f"(d2), "+f"(d3)
        : "r"(a0), "r"(a1), "r"(a2), "r"(a3), "r"(b0), "r"(b1));
}

// ---------------- setup: init counters + dtype detect + weight cvt ----------------
__global__ void k_setup(const unsigned int* ei_words,
                        const float* __restrict__ W1, const float* __restrict__ W2,
                        const float* __restrict__ W3) {
    int gid = blockIdx.x * blockDim.x + threadIdx.x;
    if (gid < NN) g_cnt[gid] = 0;
    if (gid < NG * HID) g_sums[gid] = 0.0f;
    if (gid < NG) g_cnts[gid] = 0.0f;

    if (blockIdx.x == 0) {
        __shared__ int any_nz;
        if (threadIdx.x == 0) any_nz = 0;
        __syncthreads();
        unsigned int w = ei_words[2 * threadIdx.x + 1];
        if (w) atomicOr(&any_nz, 1);
        __syncthreads();
        if (threadIdx.x == 0) g_i64 = any_nz ? 0 : 1;
    } else if (blockIdx.x == 1) {
        int t = threadIdx.x;
        for (int i = t; i < HID * 32; i += 256) {
            int n = i >> 5, k = i & 31;
            g_wt1[i] = __float2half_rn((k < FIN) ? W1[k * HID + n] : 0.0f);
        }
        for (int i = t; i < HID * HID; i += 256) {
            int n = i >> 6, k = i & 63;
            g_wt2[i] = __float2half_rn(W2[k * HID + n]);
            g_wt3[i] = __float2half_rn(W3[k * HID + n]);
        }
    }
}

// ---------------- single-pass padded-bucket fill, 4 edges/thread ------------------
__global__ void k_fillp(const void* ei) {
    long long base = (long long)(blockIdx.x * blockDim.x + threadIdx.x) * 4;
    if (base >= NE) return;      // NE % 4 == 0 -> full quads always
    int is64 = g_i64;
    int s0 = ld_idx(ei, base + 0, is64);
    int s1 = ld_idx(ei, base + 1, is64);
    int s2 = ld_idx(ei, base + 2, is64);
    int s3 = ld_idx(ei, base + 3, is64);
    int d0 = ld_idx(ei, NE + base + 0, is64);
    int d1 = ld_idx(ei, NE + base + 1, is64);
    int d2 = ld_idx(ei, NE + base + 2, is64);
    int d3 = ld_idx(ei, NE + base + 3, is64);
    int p0 = atomicAdd(&g_cnt[d0], 1);
    int p1 = atomicAdd(&g_cnt[d1], 1);
    int p2 = atomicAdd(&g_cnt[d2], 1);
    int p3 = atomicAdd(&g_cnt[d3], 1);
    g_esrc[d0 * BKT + p0] = s0;
    g_esrc[d1 * BKT + p1] = s1;
    g_esrc[d2 * BKT + p2] = s2;
    g_esrc[d3 * BKT + p3] = s3;
}

// ---------------- x -> dinv-scaled fp16 (computes + stores dinv too) ---------------
__global__ void k_x2h(const float* __restrict__ x) {
    int gid = blockIdx.x * blockDim.x + threadIdx.x;
    if (gid >= NN * 32) return;
    int node = gid >> 5;
    int f = gid & 31;
    float di = rsqrtf((float)g_cnt[node] + 1.0f);
    if (f == 0) g_dinv[node] = di;
    float v = (f < FIN) ? di * x[(long long)node * FIN + f] : 0.0f;
    g_x16[gid] = __float2half_rn(v);
}

// ---------------- fused layer 1: gather(x') + HMMA GEMM (Kp=32) -> g_h16 -------------
// block = 16 nodes, 256 threads
#define S1 40   // Xs stride in halves (32 + 8 pad, conflict-free)
__global__ void k_layer1(const float* __restrict__ b) {
    __shared__ __align__(16) __half Xs[16 * S1];
    int t = threadIdx.x;
    int n0 = blockIdx.x * 16;
    int node = n0 + (t >> 4);
    int c = t & 15;

    float di = (node < NN) ? g_dinv[node] : 0.0f;

    // ---- gather: threads c=0..9 own dims [2c,2c+1]; fp16 tree over 4 edges ----
    float2 acc = make_float2(0.f, 0.f);
    if (node < NN && c < 10) {
        unsigned own = *(const unsigned*)&g_x16[node * 32 + c * 2];
        float2 f = __half22float2(*(const __half2*)&own);
        acc.x = f.x; acc.y = f.y;
        int deg = g_cnt[node];
        int e0 = node * BKT;
        int e = e0, e4 = e0 + (deg & ~3), e1 = e0 + deg;
        for (; e < e4; e += 4) {
            int s0 = g_esrc[e];
            int s1 = g_esrc[e + 1];
            int s2 = g_esrc[e + 2];
            int s3 = g_esrc[e + 3];
            unsigned u0 = *(const unsigned*)&g_x16[s0 * 32 + c * 2];
            unsigned u1 = *(const unsigned*)&g_x16[s1 * 32 + c * 2];
            unsigned u2 = *(const unsigned*)&g_x16[s2 * 32 + c * 2];
            unsigned u3 = *(const unsigned*)&g_x16[s3 * 32 + c * 2];
            unsigned u = haddu(haddu(u0, u1), haddu(u2, u3));
            float2 fu = __half22float2(*(const __half2*)&u);
            acc.x += fu.x; acc.y += fu.y;
        }
        for (; e < e1; e++) {
            int s0 = g_esrc[e];
            unsigned u = *(const unsigned*)&g_x16[s0 * 32 + c * 2];
            float2 fu = __half22float2(*(const __half2*)&u);
            acc.x += fu.x; acc.y += fu.y;
        }
        acc.x *= di; acc.y *= di;
    }
    {
        __half2 p = __floats2half2_rn(acc.x, acc.y);
        *(unsigned*)&Xs[(t >> 4) * S1 + c * 2] = *(unsigned*)&p;
    }
    __syncthreads();

    // ---- HMMA GEMM: warp w -> n-tile w (8 cols), K=32 (2 ksteps) ----
    int w = t >> 5;
    int lane = t & 31;
    int gid = lane >> 2, tig = lane & 3;
    float2 bb = *(const float2*)&b[w * 8 + tig * 2];
    float d0 = bb.x, d1 = bb.y, d2 = bb.x, d3 = bb.y;
#pragma unroll
    for (int kk = 0; kk < 2; kk++) {
        int ka = kk * 16 + tig * 2;
        unsigned a0 = *(const unsigned*)&Xs[gid * S1 + ka];
        unsigned a1 = *(const unsigned*)&Xs[(gid + 8) * S1 + ka];
        unsigned a2 = *(const unsigned*)&Xs[gid * S1 + ka + 8];
        unsigned a3 = *(const unsigned*)&Xs[(gid + 8) * S1 + ka + 8];
        unsigned b0 = *(const unsigned*)&g_wt1[(w * 8 + gid) * 32 + ka];
        unsigned b1 = *(const unsigned*)&g_wt1[(w * 8 + gid) * 32 + ka + 8];
        mma16816(d0, d1, d2, d3, a0, a1, a2, a3, b0, b1);
    }
    // epilogue: relu, pre-scale by dinv, store fp16
    int r0 = n0 + gid, r1 = n0 + gid + 8;
    if (r0 < NN) {
        float s = g_dinv[r0];
        __half2 p = __floats2half2_rn(s * fmaxf(d0, 0.f), s * fmaxf(d1, 0.f));
        *(unsigned*)&g_h16[r0 * HID + w * 8 + tig * 2] = *(unsigned*)&p;
    }
    if (r1 < NN) {
        float s = g_dinv[r1];
        __half2 p = __floats2half2_rn(s * fmaxf(d2, 0.f), s * fmaxf(d3, 0.f));
        *(unsigned*)&g_h16[r1 * HID + w * 8 + tig * 2] = *(unsigned*)&p;
    }
}

// ---------------- fused hidden layer: gather + HMMA GEMM (+ optional pool) -----------
// block = 16 nodes, 256 threads
#define SH 72   // Xs stride in halves (64 + 8 pad, conflict-free)
template <bool DO_POOL>
__global__ void k_layerh(const __half* __restrict__ hin, __half* __restrict__ hout,
                         const __half* __restrict__ Wt, const float* __restrict__ b,
                         const void* batch) {
    __shared__ __align__(16) __half Xs[16 * SH];
    __shared__ float Hs[16 * HID];
    int t = threadIdx.x;
    int n0 = blockIdx.x * 16;
    int node = n0 + (t >> 4);
    int c = t & 15;

    float di = (node < NN) ? g_dinv[node] : 0.0f;

    // ---- phase 1: gather with fp16 pre-reduction tree over 4 edges ----
    {
        float acc[4] = {0, 0, 0, 0};
        if (node < NN) {
            uint2 own = *(const uint2*)&hin[node * HID + c * 4];
            add4_h(own, acc);
            int deg = g_cnt[node];
            int e0 = node * BKT;
            int e = e0, e4 = e0 + (deg & ~3), e1 = e0 + deg;
            for (; e < e4; e += 4) {
                int s0 = g_esrc[e];
                int s1 = g_esrc[e + 1];
                int s2 = g_esrc[e + 2];
                int s3 = g_esrc[e + 3];
                uint2 u0 = *(const uint2*)&hin[s0 * HID + c * 4];
                uint2 u1 = *(const uint2*)&hin[s1 * HID + c * 4];
                uint2 u2 = *(const uint2*)&hin[s2 * HID + c * 4];
                uint2 u3 = *(const uint2*)&hin[s3 * HID + c * 4];
                uint2 u = hadd2x2(hadd2x2(u0, u1), hadd2x2(u2, u3));
                add4_h(u, acc);
            }
            for (; e < e1; e++) {
                int s0 = g_esrc[e];
                uint2 u = *(const uint2*)&hin[s0 * HID + c * 4];
                add4_h(u, acc);
            }
        }
        __half2 p0 = __floats2half2_rn(di * acc[0], di * acc[1]);
        __half2 p1 = __floats2half2_rn(di * acc[2], di * acc[3]);
        uint2 pk = make_uint2(*(unsigned*)&p0, *(unsigned*)&p1);
        *(uint2*)&Xs[(t >> 4) * SH + c * 4] = pk;
    }
    __syncthreads();

    // ---- phase 2: HMMA GEMM: warp w -> n-tile w, K=64 (4 ksteps) ----
    int w = t >> 5;
    int lane = t & 31;
    int gid = lane >> 2, tig = lane & 3;
    float2 bb = *(const float2*)&b[w * 8 + tig * 2];
    float d0 = bb.x, d1 = bb.y, d2 = bb.x, d3 = bb.y;
#pragma unroll
    for (int kk = 0; kk < 4; kk++) {
        int ka = kk * 16 + tig * 2;
        unsigned a0 = *(const unsigned*)&Xs[gid * SH + ka];
        unsigned a1 = *(const unsigned*)&Xs[(gid + 8) * SH + ka];
        unsigned a2 = *(const unsigned*)&Xs[gid * SH + ka + 8];
        unsigned a3 = *(const unsigned*)&Xs[(gid + 8) * SH + ka + 8];
        unsigned b0 = *(const unsigned*)&Wt[(w * 8 + gid) * HID + ka];
        unsigned b1 = *(const unsigned*)&Wt[(w * 8 + gid) * HID + ka + 8];
        mma16816(d0, d1, d2, d3, a0, a1, a2, a3, b0, b1);
    }
    d0 = fmaxf(d0, 0.f); d1 = fmaxf(d1, 0.f);
    d2 = fmaxf(d2, 0.f); d3 = fmaxf(d3, 0.f);

    int r0 = n0 + gid, r1 = n0 + gid + 8;
    if (!DO_POOL) {
        if (r0 < NN) {
            float s = g_dinv[r0];
            __half2 p = __floats2half2_rn(s * d0, s * d1);
            *(unsigned*)&hout[r0 * HID + w * 8 + tig * 2] = *(unsigned*)&p;
        }
        if (r1 < NN) {
            float s = g_dinv[r1];
            __half2 p = __floats2half2_rn(s * d2, s * d3);
            *(unsigned*)&hout[r1 * HID + w * 8 + tig * 2] = *(unsigned*)&p;
        }
    } else {
        Hs[gid * HID + w * 8 + tig * 2]       = d0;
        Hs[gid * HID + w * 8 + tig * 2 + 1]   = d1;
        Hs[(gid + 8) * HID + w * 8 + tig * 2]     = d2;
        Hs[(gid + 8) * HID + w * 8 + tig * 2 + 1] = d3;
        __syncthreads();
        // ---- phase 3: segmented pool over this block's 16 nodes ----
        if (t < 16) {
            int lim = NN - n0; if (lim > 16) lim = 16;
            if (lim <= 0) return;
            int is64 = g_i64;
            float4 acc = make_float4(0, 0, 0, 0);
            float cnt = 0.0f;
            int cur = ld_idx(batch, n0, is64);
            for (int i = 0; i < lim; i++) {
                int g = ld_idx(batch, n0 + i, is64);
                if (g != cur) {
                    red_add_v4(&g_sums[cur * HID + t * 4], acc);
                    if (t == 0) atomicAdd(&g_cnts[cur], cnt);
                    acc = make_float4(0, 0, 0, 0);
                    cnt = 0.0f;
                    cur = g;
                }
                float4 v = *(const float4*)&Hs[i * HID + t * 4];
                acc.x += v.x; acc.y += v.y; acc.z += v.z; acc.w += v.w;
                cnt += 1.0f;
            }
            red_add_v4(&g_sums[cur * HID + t * 4], acc);
            if (t == 0) atomicAdd(&g_cnts[cur], cnt);
        }
    }
}

// ---------------- final MLP head ------------------------------------------------------
__global__ void k_mlp(const float* __restrict__ lw1, const float* __restrict__ lb1,
                      const float* __restrict__ lw2, const float* __restrict__ lb2,
                      float* __restrict__ out) {
    int g = blockIdx.x;
    int j = threadIdx.x;  // 64
    __shared__ float gs[HID];
    __shared__ float red[HID];
    float cnt = fmaxf(g_cnts[g], 1.0f);
    gs[j] = g_sums[g * HID + j] / cnt;
    __syncthreads();
    float t = lb1[j];
#pragma unroll
    for (int k = 0; k < HID; k++) t += gs[k] * lw1[k * HID + j];
    t = fmaxf(t, 0.0f);
    red[j] = t * lw2[j];
    __syncthreads();
    for (int s = 32; s > 0; s >>= 1) {
        if (j < s) red[j] += red[j + s];
        __syncthreads();
    }
    if (j == 0) out[g] = red[0] + lb2[0];
}

// ---------------- launch -----------------------------------------------------------------
extern "C" void kernel_launch(void* const* d_in, const int* in_sizes, int n_in,
                              void* d_out, int out_size) {
    const float* x   = (const float*)d_in[0];
    const float* W1  = (const float*)d_in[1];
    const float* b1  = (const float*)d_in[2];
    const float* W2  = (const float*)d_in[3];
    const float* b2  = (const float*)d_in[4];
    const float* W3  = (const float*)d_in[5];
    const float* b3  = (const float*)d_in[6];
    const float* lw1 = (const float*)d_in[7];
    const float* lb1 = (const float*)d_in[8];
    const float* lw2 = (const float*)d_in[9];
    const float* lb2 = (const float*)d_in[10];
    const void*  ei  = d_in[11];
    const void*  bat = d_in[12];

    __half* h16;  cudaGetSymbolAddress((void**)&h16,  g_h16);
    __half* h16b; cudaGetSymbolAddress((void**)&h16b, g_h16b);
    __half* wt2;  cudaGetSymbolAddress((void**)&wt2,  g_wt2);
    __half* wt3;  cudaGetSymbolAddress((void**)&wt3,  g_wt3);

    const int T = 256;
    k_setup<<<(NG * HID + T - 1) / T, T>>>((const unsigned int*)ei, W1, W2, W3);
    k_fillp<<<(NE / 4 + T - 1) / T, T>>>(ei);
    k_x2h<<<(NN * 32 + T - 1) / T, T>>>(x);

    int gNodes16 = (NN + 15) / 16;

    k_layer1<<<gNodes16, T>>>(b1);
    k_layerh<false><<<gNodes16, T>>>(h16, h16b, wt2, b2, bat);
    k_layerh<true><<<gNodes16, T>>>(h16b, h16, wt3, b3, bat);

    k_mlp<<<NG, HID>>>(lw1, lb1, lw2, lb2, (float*)d_out);
}

// round 13
// speedup vs baseline: 1.0008x; 1.0008x over previous
#include <cuda_runtime.h>
#include <cuda_fp16.h>

#define NN 100000
#define NE 1600000
#define FIN 20
#define HID 64
#define NG 2000
#define BKT 64   // padded bucket slots per node (P(deg>=64) ~ 1e-20)

// ---------------- scratch ----------------------------------------------------
__device__ int    g_cnt[NN];           // per-node real degree (excl self-loop)
__device__ float  g_dinv[NN];
__device__ int    g_esrc[NN * BKT];    // padded buckets: src ids for dst=node
__device__ __half g_x16[NN * 32];      // dinv*x in fp16, row stride 32 (20 valid)
__device__ __half g_h16[NN * HID];     // dinv*relu(h1) (fp16)
__device__ __half g_h16b[NN * HID];    // dinv*relu(h2) (fp16) — ping-pong
__device__ __half g_wt1[HID * 32];     // W1^T fp16, [n][k], k padded 20->32
__device__ __half g_wt2[HID * HID];    // W2^T fp16, [n][k]
__device__ __half g_wt3[HID * HID];    // W3^T fp16, [n][k]
__device__ float  g_sums[NG * HID];
__device__ float  g_cnts[NG];
__device__ int    g_i64;

// ---------------- helpers -----------------------------------------------------
__device__ __forceinline__ int ld_idx(const void* p, long long i, int is64) {
    return ((const int*)p)[is64 ? 2 * i : i];
}

__device__ __forceinline__ void red_add_v4(float* addr, float4 v) {
    asm volatile("red.global.add.v4.f32 [%0], {%1,%2,%3,%4};"
                 :: "l"(addr), "f"(v.x), "f"(v.y), "f"(v.z), "f"(v.w)
                 : "memory");
}

__device__ __forceinline__ void add4_h(const uint2 u, float* acc) {
    float2 f0 = __half22float2(*(const __half2*)&u.x);
    float2 f1 = __half22float2(*(const __half2*)&u.y);
    acc[0] += f0.x; acc[1] += f0.y;
    acc[2] += f1.x; acc[3] += f1.y;
}

__device__ __forceinline__ uint2 hadd2x2(uint2 a, uint2 b) {
    __half2 lo = __hadd2(*(const __half2*)&a.x, *(const __half2*)&b.x);
    __half2 hi = __hadd2(*(const __half2*)&a.y, *(const __half2*)&b.y);
    uint2 r; r.x = *(unsigned*)&lo; r.y = *(unsigned*)&hi; return r;
}

__device__ __forceinline__ unsigned haddu(unsigned a, unsigned b) {
    __half2 r = __hadd2(*(const __half2*)&a, *(const __half2*)&b);
    return *(unsigned*)&r;
}

__device__ __forceinline__ void mma16816(float& d0, float& d1, float& d2, float& d3,
                                         unsigned a0, unsigned a1, unsigned a2, unsigned a3,
                                         unsigned b0, unsigned b1) {
    asm volatile(
        "mma.sync.aligned.m16n8k16.row.col.f32.f16.f16.f32 "
        "{%0,%1,%2,%3}, {%4,%5,%6,%7}, {%8,%9}, {%0,%1,%2,%3};"
        : "+f"(d0), "+f"(d1), "+f"(d2), "+f"(d3)
        : "r"(a0), "r"(a1), "r"(a2), "r"(a3), "r"(b0), "r"(b1));
}

// ---------------- setup: init counters + dtype detect + weight cvt ----------------
__global__ void k_setup(const unsigned int* ei_words,
                        const float* __restrict__ W1, const float* __restrict__ W2,
                        const float* __restrict__ W3) {
    int gid = blockIdx.x * blockDim.x + threadIdx.x;
    if (gid < NN) g_cnt[gid] = 0;
    if (gid < NG * HID) g_sums[gid] = 0.0f;
    if (gid < NG) g_cnts[gid] = 0.0f;

    if (blockIdx.x == 0) {
        __shared__ int any_nz;
        if (threadIdx.x == 0) any_nz = 0;
        __syncthreads();
        unsigned int w = ei_words[2 * threadIdx.x + 1];
        if (w) atomicOr(&any_nz, 1);
        __syncthreads();
        if (threadIdx.x == 0) g_i64 = any_nz ? 0 : 1;
    } else if (blockIdx.x == 1) {
        int t = threadIdx.x;
        for (int i = t; i < HID * 32; i += 256) {
            int n = i >> 5, k = i & 31;
            g_wt1[i] = __float2half_rn((k < FIN) ? W1[k * HID + n] : 0.0f);
        }
        for (int i = t; i < HID * HID; i += 256) {
            int n = i >> 6, k = i & 63;
            g_wt2[i] = __float2half_rn(W2[k * HID + n]);
            g_wt3[i] = __float2half_rn(W3[k * HID + n]);
        }
    }
}

// ---------------- single-pass padded-bucket fill, 4 edges/thread ------------------
__global__ void k_fillp(const void* ei) {
    long long base = (long long)(blockIdx.x * blockDim.x + threadIdx.x) * 4;
    if (base >= NE) return;      // NE % 4 == 0 -> full quads always
    int is64 = g_i64;
    int s0 = ld_idx(ei, base + 0, is64);
    int s1 = ld_idx(ei, base + 1, is64);
    int s2 = ld_idx(ei, base + 2, is64);
    int s3 = ld_idx(ei, base + 3, is64);
    int d0 = ld_idx(ei, NE + base + 0, is64);
    int d1 = ld_idx(ei, NE + base + 1, is64);
    int d2 = ld_idx(ei, NE + base + 2, is64);
    int d3 = ld_idx(ei, NE + base + 3, is64);
    int p0 = atomicAdd(&g_cnt[d0], 1);
    int p1 = atomicAdd(&g_cnt[d1], 1);
    int p2 = atomicAdd(&g_cnt[d2], 1);
    int p3 = atomicAdd(&g_cnt[d3], 1);
    g_esrc[d0 * BKT + p0] = s0;
    g_esrc[d1 * BKT + p1] = s1;
    g_esrc[d2 * BKT + p2] = s2;
    g_esrc[d3 * BKT + p3] = s3;
}

// ---------------- x -> dinv-scaled fp16 (computes + stores dinv too) ---------------
__global__ void k_x2h(const float* __restrict__ x) {
    int gid = blockIdx.x * blockDim.x + threadIdx.x;
    if (gid >= NN * 32) return;
    int node = gid >> 5;
    int f = gid & 31;
    float di = rsqrtf((float)g_cnt[node] + 1.0f);
    if (f == 0) g_dinv[node] = di;
    float v = (f < FIN) ? di * x[(long long)node * FIN + f] : 0.0f;
    g_x16[gid] = __float2half_rn(v);
}

// ---------------- fused layer 1: gather(x') + HMMA GEMM (Kp=32) -> g_h16 -------------
// block = 16 nodes, 256 threads
#define S1 40   // Xs stride in halves (32 + 8 pad, conflict-free)
__global__ void k_layer1(const float* __restrict__ b) {
    __shared__ __align__(16) __half Xs[16 * S1];
    int t = threadIdx.x;
    int n0 = blockIdx.x * 16;
    int node = n0 + (t >> 4);
    int c = t & 15;

    float di = (node < NN) ? g_dinv[node] : 0.0f;

    // ---- gather: threads c=0..9 own dims [2c,2c+1]; fp16 pair-merge per 2 edges ----
    float2 acc = make_float2(0.f, 0.f);
    if (node < NN && c < 10) {
        unsigned own = *(const unsigned*)&g_x16[node * 32 + c * 2];
        float2 f = __half22float2(*(const __half2*)&own);
        acc.x = f.x; acc.y = f.y;
        int e0 = node * BKT;
        int e1 = e0 + g_cnt[node];
        int e = e0;
        for (; e + 1 < e1; e += 2) {
            int s0 = g_esrc[e];
            int s1 = g_esrc[e + 1];
            unsigned u0 = *(const unsigned*)&g_x16[s0 * 32 + c * 2];
            unsigned u1 = *(const unsigned*)&g_x16[s1 * 32 + c * 2];
            unsigned u = haddu(u0, u1);
            float2 fu = __half22float2(*(const __half2*)&u);
            acc.x += fu.x; acc.y += fu.y;
        }
        if (e < e1) {
            int s0 = g_esrc[e];
            unsigned u = *(const unsigned*)&g_x16[s0 * 32 + c * 2];
            float2 fu = __half22float2(*(const __half2*)&u);
            acc.x += fu.x; acc.y += fu.y;
        }
        acc.x *= di; acc.y *= di;
    }
    {
        __half2 p = __floats2half2_rn(acc.x, acc.y);
        *(unsigned*)&Xs[(t >> 4) * S1 + c * 2] = *(unsigned*)&p;
    }
    __syncthreads();

    // ---- HMMA GEMM: warp w -> n-tile w (8 cols), K=32 (2 ksteps) ----
    int w = t >> 5;
    int lane = t & 31;
    int gid = lane >> 2, tig = lane & 3;
    float2 bb = *(const float2*)&b[w * 8 + tig * 2];
    float d0 = bb.x, d1 = bb.y, d2 = bb.x, d3 = bb.y;
#pragma unroll
    for (int kk = 0; kk < 2; kk++) {
        int ka = kk * 16 + tig * 2;
        unsigned a0 = *(const unsigned*)&Xs[gid * S1 + ka];
        unsigned a1 = *(const unsigned*)&Xs[(gid + 8) * S1 + ka];
        unsigned a2 = *(const unsigned*)&Xs[gid * S1 + ka + 8];
        unsigned a3 = *(const unsigned*)&Xs[(gid + 8) * S1 + ka + 8];
        unsigned b0 = *(const unsigned*)&g_wt1[(w * 8 + gid) * 32 + ka];
        unsigned b1 = *(const unsigned*)&g_wt1[(w * 8 + gid) * 32 + ka + 8];
        mma16816(d0, d1, d2, d3, a0, a1, a2, a3, b0, b1);
    }
    // epilogue: relu, pre-scale by dinv, store fp16
    int r0 = n0 + gid, r1 = n0 + gid + 8;
    if (r0 < NN) {
        float s = g_dinv[r0];
        __half2 p = __floats2half2_rn(s * fmaxf(d0, 0.f), s * fmaxf(d1, 0.f));
        *(unsigned*)&g_h16[r0 * HID + w * 8 + tig * 2] = *(unsigned*)&p;
    }
    if (r1 < NN) {
        float s = g_dinv[r1];
        __half2 p = __floats2half2_rn(s * fmaxf(d2, 0.f), s * fmaxf(d3, 0.f));
        *(unsigned*)&g_h16[r1 * HID + w * 8 + tig * 2] = *(unsigned*)&p;
    }
}

// ---------------- fused hidden layer: gather + HMMA GEMM (+ optional pool) -----------
// block = 16 nodes, 256 threads
#define SH 72   // Xs stride in halves (64 + 8 pad, conflict-free)
template <bool DO_POOL>
__global__ void k_layerh(const __half* __restrict__ hin, __half* __restrict__ hout,
                         const __half* __restrict__ Wt, const float* __restrict__ b,
                         const void* batch) {
    __shared__ __align__(16) __half Xs[16 * SH];
    __shared__ float Hs[16 * HID];
    int t = threadIdx.x;
    int n0 = blockIdx.x * 16;
    int node = n0 + (t >> 4);
    int c = t & 15;

    float di = (node < NN) ? g_dinv[node] : 0.0f;

    // ---- phase 1: gather with fp16 pair-merge per 2 edges ----
    {
        float acc[4] = {0, 0, 0, 0};
        if (node < NN) {
            uint2 own = *(const uint2*)&hin[node * HID + c * 4];
            add4_h(own, acc);
            int e0 = node * BKT;
            int e1 = e0 + g_cnt[node];
            int e = e0;
            for (; e + 1 < e1; e += 2) {
                int s0 = g_esrc[e];
                int s1 = g_esrc[e + 1];
                uint2 u0 = *(const uint2*)&hin[s0 * HID + c * 4];
                uint2 u1 = *(const uint2*)&hin[s1 * HID + c * 4];
                add4_h(hadd2x2(u0, u1), acc);
            }
            if (e < e1) {
                int s0 = g_esrc[e];
                uint2 u = *(const uint2*)&hin[s0 * HID + c * 4];
                add4_h(u, acc);
            }
        }
        __half2 p0 = __floats2half2_rn(di * acc[0], di * acc[1]);
        __half2 p1 = __floats2half2_rn(di * acc[2], di * acc[3]);
        uint2 pk = make_uint2(*(unsigned*)&p0, *(unsigned*)&p1);
        *(uint2*)&Xs[(t >> 4) * SH + c * 4] = pk;
    }
    __syncthreads();

    // ---- phase 2: HMMA GEMM: warp w -> n-tile w, K=64 (4 ksteps) ----
    int w = t >> 5;
    int lane = t & 31;
    int gid = lane >> 2, tig = lane & 3;
    float2 bb = *(const float2*)&b[w * 8 + tig * 2];
    float d0 = bb.x, d1 = bb.y, d2 = bb.x, d3 = bb.y;
#pragma unroll
    for (int kk = 0; kk < 4; kk++) {
        int ka = kk * 16 + tig * 2;
        unsigned a0 = *(const unsigned*)&Xs[gid * SH + ka];
        unsigned a1 = *(const unsigned*)&Xs[(gid + 8) * SH + ka];
        unsigned a2 = *(const unsigned*)&Xs[gid * SH + ka + 8];
        unsigned a3 = *(const unsigned*)&Xs[(gid + 8) * SH + ka + 8];
        unsigned b0 = *(const unsigned*)&Wt[(w * 8 + gid) * HID + ka];
        unsigned b1 = *(const unsigned*)&Wt[(w * 8 + gid) * HID + ka + 8];
        mma16816(d0, d1, d2, d3, a0, a1, a2, a3, b0, b1);
    }
    d0 = fmaxf(d0, 0.f); d1 = fmaxf(d1, 0.f);
    d2 = fmaxf(d2, 0.f); d3 = fmaxf(d3, 0.f);

    int r0 = n0 + gid, r1 = n0 + gid + 8;
    if (!DO_POOL) {
        if (r0 < NN) {
            float s = g_dinv[r0];
            __half2 p = __floats2half2_rn(s * d0, s * d1);
            *(unsigned*)&hout[r0 * HID + w * 8 + tig * 2] = *(unsigned*)&p;
        }
        if (r1 < NN) {
            float s = g_dinv[r1];
            __half2 p = __floats2half2_rn(s * d2, s * d3);
            *(unsigned*)&hout[r1 * HID + w * 8 + tig * 2] = *(unsigned*)&p;
        }
    } else {
        Hs[gid * HID + w * 8 + tig * 2]       = d0;
        Hs[gid * HID + w * 8 + tig * 2 + 1]   = d1;
        Hs[(gid + 8) * HID + w * 8 + tig * 2]     = d2;
        Hs[(gid + 8) * HID + w * 8 + tig * 2 + 1] = d3;
        __syncthreads();
        // ---- phase 3: segmented pool over this block's 16 nodes ----
        if (t < 16) {
            int lim = NN - n0; if (lim > 16) lim = 16;
            if (lim <= 0) return;
            int is64 = g_i64;
            float4 acc = make_float4(0, 0, 0, 0);
            float cnt = 0.0f;
            int cur = ld_idx(batch, n0, is64);
            for (int i = 0; i < lim; i++) {
                int g = ld_idx(batch, n0 + i, is64);
                if (g != cur) {
                    red_add_v4(&g_sums[cur * HID + t * 4], acc);
                    if (t == 0) atomicAdd(&g_cnts[cur], cnt);
                    acc = make_float4(0, 0, 0, 0);
                    cnt = 0.0f;
                    cur = g;
                }
                float4 v = *(const float4*)&Hs[i * HID + t * 4];
                acc.x += v.x; acc.y += v.y; acc.z += v.z; acc.w += v.w;
                cnt += 1.0f;
            }
            red_add_v4(&g_sums[cur * HID + t * 4], acc);
            if (t == 0) atomicAdd(&g_cnts[cur], cnt);
        }
    }
}

// ---------------- final MLP head ------------------------------------------------------
__global__ void k_mlp(const float* __restrict__ lw1, const float* __restrict__ lb1,
                      const float* __restrict__ lw2, const float* __restrict__ lb2,
                      float* __restrict__ out) {
    int g = blockIdx.x;
    int j = threadIdx.x;  // 64
    __shared__ float gs[HID];
    __shared__ float red[HID];
    float cnt = fmaxf(g_cnts[g], 1.0f);
    gs[j] = g_sums[g * HID + j] / cnt;
    __syncthreads();
    float t = lb1[j];
#pragma unroll
    for (int k = 0; k < HID; k++) t += gs[k] * lw1[k * HID + j];
    t = fmaxf(t, 0.0f);
    red[j] = t * lw2[j];
    __syncthreads();
    for (int s = 32; s > 0; s >>= 1) {
        if (j < s) red[j] += red[j + s];
        __syncthreads();
    }
    if (j == 0) out[g] = red[0] + lb2[0];
}

// ---------------- launch -----------------------------------------------------------------
extern "C" void kernel_launch(void* const* d_in, const int* in_sizes, int n_in,
                              void* d_out, int out_size) {
    const float* x   = (const float*)d_in[0];
    const float* W1  = (const float*)d_in[1];
    const float* b1  = (const float*)d_in[2];
    const float* W2  = (const float*)d_in[3];
    const float* b2  = (const float*)d_in[4];
    const float* W3  = (const float*)d_in[5];
    const float* b3  = (const float*)d_in[6];
    const float* lw1 = (const float*)d_in[7];
    const float* lb1 = (const float*)d_in[8];
    const float* lw2 = (const float*)d_in[9];
    const float* lb2 = (const float*)d_in[10];
    const void*  ei  = d_in[11];
    const void*  bat = d_in[12];

    __half* h16;  cudaGetSymbolAddress((void**)&h16,  g_h16);
    __half* h16b; cudaGetSymbolAddress((void**)&h16b, g_h16b);
    __half* wt2;  cudaGetSymbolAddress((void**)&wt2,  g_wt2);
    __half* wt3;  cudaGetSymbolAddress((void**)&wt3,  g_wt3);

    const int T = 256;
    k_setup<<<(NG * HID + T - 1) / T, T>>>((const unsigned int*)ei, W1, W2, W3);
    k_fillp<<<(NE / 4 + T - 1) / T, T>>>(ei);
    k_x2h<<<(NN * 32 + T - 1) / T, T>>>(x);

    int gNodes16 = (NN + 15) / 16;

    k_layer1<<<gNodes16, T>>>(b1);
    k_layerh<false><<<gNodes16, T>>>(h16, h16b, wt2, b2, bat);
    k_layerh<true><<<gNodes16, T>>>(h16b, h16, wt3, b3, bat);

    k_mlp<<<NG, HID>>>(lw1, lb1, lw2, lb2, (float*)d_out);
}

// round 14
// speedup vs baseline: 1.1290x; 1.1281x over previous
#include <cuda_runtime.h>
#include <cuda_fp16.h>

#define NN 100000
#define NE 1600000
#define FIN 20
#define HID 64
#define NG 2000
#define BKT 64   // padded bucket slots per node (P(deg>=64) ~ 1e-20)

// ---------------- scratch ----------------------------------------------------
__device__ int    g_cnt[NN];           // per-node real degree (excl self-loop)
__device__ float  g_dinv[NN];
__device__ int    g_esrc[NN * BKT];    // padded buckets: src ids for dst=node
__device__ __half g_x16[NN * 32];      // dinv*x in fp16, row stride 32 (20 valid)
__device__ __half g_h16[NN * HID];     // dinv*relu(h1) (fp16)
__device__ __half g_h16b[NN * HID];    // dinv*relu(h2) (fp16) — ping-pong
__device__ __half g_wt1[HID * 32];     // W1^T fp16, [n][k], k padded 20->32
__device__ __half g_wt2[HID * HID];    // W2^T fp16, [n][k]
__device__ __half g_wt3[HID * HID];    // W3^T fp16, [n][k]
__device__ float  g_sums[NG * HID];
__device__ float  g_cnts[NG];
__device__ int    g_i64;

// ---------------- helpers -----------------------------------------------------
__device__ __forceinline__ int ld_idx(const void* p, long long i, int is64) {
    return ((const int*)p)[is64 ? 2 * i : i];
}

__device__ __forceinline__ void red_add_v4(float* addr, float4 v) {
    asm volatile("red.global.add.v4.f32 [%0], {%1,%2,%3,%4};"
                 :: "l"(addr), "f"(v.x), "f"(v.y), "f"(v.z), "f"(v.w)
                 : "memory");
}

__device__ __forceinline__ void add4_h(const uint2 u, float* acc) {
    float2 f0 = __half22float2(*(const __half2*)&u.x);
    float2 f1 = __half22float2(*(const __half2*)&u.y);
    acc[0] += f0.x; acc[1] += f0.y;
    acc[2] += f1.x; acc[3] += f1.y;
}

__device__ __forceinline__ void mma16816(float& d0, float& d1, float& d2, float& d3,
                                         unsigned a0, unsigned a1, unsigned a2, unsigned a3,
                                         unsigned b0, unsigned b1) {
    asm volatile(
        "mma.sync.aligned.m16n8k16.row.col.f32.f16.f16.f32 "
        "{%0,%1,%2,%3}, {%4,%5,%6,%7}, {%8,%9}, {%0,%1,%2,%3};"
        : "+f"(d0), "+f"(d1), "+f"(d2), "+f"(d3)
        : "r"(a0), "r"(a1), "r"(a2), "r"(a3), "r"(b0), "r"(b1));
}

// ---------------- setup: init counters + dtype detect + weight cvt ----------------
__global__ void k_setup(const unsigned int* ei_words,
                        const float* __restrict__ W1, const float* __restrict__ W2,
                        const float* __restrict__ W3) {
    int gid = blockIdx.x * blockDim.x + threadIdx.x;
    if (gid < NN) g_cnt[gid] = 0;
    if (gid < NG * HID) g_sums[gid] = 0.0f;
    if (gid < NG) g_cnts[gid] = 0.0f;

    if (blockIdx.x == 0) {
        __shared__ int any_nz;
        if (threadIdx.x == 0) any_nz = 0;
        __syncthreads();
        unsigned int w = ei_words[2 * threadIdx.x + 1];
        if (w) atomicOr(&any_nz, 1);
        __syncthreads();
        if (threadIdx.x == 0) g_i64 = any_nz ? 0 : 1;
    } else if (blockIdx.x == 1) {
        int t = threadIdx.x;
        for (int i = t; i < HID * 32; i += 256) {
            int n = i >> 5, k = i & 31;
            g_wt1[i] = __float2half_rn((k < FIN) ? W1[k * HID + n] : 0.0f);
        }
        for (int i = t; i < HID * HID; i += 256) {
            int n = i >> 6, k = i & 63;
            g_wt2[i] = __float2half_rn(W2[k * HID + n]);
            g_wt3[i] = __float2half_rn(W3[k * HID + n]);
        }
    }
}

// ---------------- single-pass padded-bucket fill, 4 edges/thread ------------------
__global__ void k_fillp(const void* ei) {
    long long base = (long long)(blockIdx.x * blockDim.x + threadIdx.x) * 4;
    if (base >= NE) return;      // NE % 4 == 0 -> full quads always
    int is64 = g_i64;
    int s0 = ld_idx(ei, base + 0, is64);
    int s1 = ld_idx(ei, base + 1, is64);
    int s2 = ld_idx(ei, base + 2, is64);
    int s3 = ld_idx(ei, base + 3, is64);
    int d0 = ld_idx(ei, NE + base + 0, is64);
    int d1 = ld_idx(ei, NE + base + 1, is64);
    int d2 = ld_idx(ei, NE + base + 2, is64);
    int d3 = ld_idx(ei, NE + base + 3, is64);
    int p0 = atomicAdd(&g_cnt[d0], 1);
    int p1 = atomicAdd(&g_cnt[d1], 1);
    int p2 = atomicAdd(&g_cnt[d2], 1);
    int p3 = atomicAdd(&g_cnt[d3], 1);
    g_esrc[d0 * BKT + p0] = s0;
    g_esrc[d1 * BKT + p1] = s1;
    g_esrc[d2 * BKT + p2] = s2;
    g_esrc[d3 * BKT + p3] = s3;
}

// ---------------- x -> dinv-scaled fp16 (computes + stores dinv too) ---------------
__global__ void k_x2h(const float* __restrict__ x) {
    int gid = blockIdx.x * blockDim.x + threadIdx.x;
    if (gid >= NN * 32) return;
    int node = gid >> 5;
    int f = gid & 31;
    float di = rsqrtf((float)g_cnt[node] + 1.0f);
    if (f == 0) g_dinv[node] = di;
    float v = (f < FIN) ? di * x[(long long)node * FIN + f] : 0.0f;
    g_x16[gid] = __float2half_rn(v);
}

// ---------------- fused layer 1: gather(x') + HMMA GEMM (Kp=32) -> g_h16 -------------
// block = 16 nodes, 256 threads
#define S1 40   // Xs stride in halves (32 + 8 pad, conflict-free)
__global__ void k_layer1(const float* __restrict__ b) {
    __shared__ __align__(16) __half Xs[16 * S1];
    int t = threadIdx.x;
    int n0 = blockIdx.x * 16;
    int node = n0 + (t >> 4);
    int c = t & 15;

    float di = (node < NN) ? g_dinv[node] : 0.0f;

    // ---- gather: threads c=0..9 own dims [2c,2c+1]; prefetched indices ----
    float2 acc = make_float2(0.f, 0.f);
    if (node < NN && c < 10) {
        unsigned own = *(const unsigned*)&g_x16[node * 32 + c * 2];
        float2 f = __half22float2(*(const __half2*)&own);
        acc.x = f.x; acc.y = f.y;
        int e0 = node * BKT;
        int e1 = e0 + g_cnt[node];
        int e = e0;
        // prefetch first pair (over-read safe inside 64-slot bucket)
        int s0 = g_esrc[e];
        int s1 = g_esrc[e + 1];
        for (; e + 1 < e1; e += 2) {
            unsigned u0 = *(const unsigned*)&g_x16[s0 * 32 + c * 2];
            unsigned u1 = *(const unsigned*)&g_x16[s1 * 32 + c * 2];
            s0 = g_esrc[e + 2];             // next pair, overlaps payload latency
            s1 = g_esrc[e + 3];
            float2 f0 = __half22float2(*(const __half2*)&u0);
            float2 f1 = __half22float2(*(const __half2*)&u1);
            acc.x += f0.x + f1.x;
            acc.y += f0.y + f1.y;
        }
        if (e < e1) {                        // s0 == g_esrc[e] from prefetch
            unsigned u = *(const unsigned*)&g_x16[s0 * 32 + c * 2];
            float2 f0 = __half22float2(*(const __half2*)&u);
            acc.x += f0.x; acc.y += f0.y;
        }
        acc.x *= di; acc.y *= di;
    }
    {
        __half2 p = __floats2half2_rn(acc.x, acc.y);
        *(unsigned*)&Xs[(t >> 4) * S1 + c * 2] = *(unsigned*)&p;
    }
    __syncthreads();

    // ---- HMMA GEMM: warp w -> n-tile w (8 cols), K=32 (2 ksteps) ----
    int w = t >> 5;
    int lane = t & 31;
    int gid = lane >> 2, tig = lane & 3;
    float2 bb = *(const float2*)&b[w * 8 + tig * 2];
    float d0 = bb.x, d1 = bb.y, d2 = bb.x, d3 = bb.y;
#pragma unroll
    for (int kk = 0; kk < 2; kk++) {
        int ka = kk * 16 + tig * 2;
        unsigned a0 = *(const unsigned*)&Xs[gid * S1 + ka];
        unsigned a1 = *(const unsigned*)&Xs[(gid + 8) * S1 + ka];
        unsigned a2 = *(const unsigned*)&Xs[gid * S1 + ka + 8];
        unsigned a3 = *(const unsigned*)&Xs[(gid + 8) * S1 + ka + 8];
        unsigned b0 = *(const unsigned*)&g_wt1[(w * 8 + gid) * 32 + ka];
        unsigned b1 = *(const unsigned*)&g_wt1[(w * 8 + gid) * 32 + ka + 8];
        mma16816(d0, d1, d2, d3, a0, a1, a2, a3, b0, b1);
    }
    // epilogue: relu, pre-scale by dinv, store fp16
    int r0 = n0 + gid, r1 = n0 + gid + 8;
    if (r0 < NN) {
        float s = g_dinv[r0];
        __half2 p = __floats2half2_rn(s * fmaxf(d0, 0.f), s * fmaxf(d1, 0.f));
        *(unsigned*)&g_h16[r0 * HID + w * 8 + tig * 2] = *(unsigned*)&p;
    }
    if (r1 < NN) {
        float s = g_dinv[r1];
        __half2 p = __floats2half2_rn(s * fmaxf(d2, 0.f), s * fmaxf(d3, 0.f));
        *(unsigned*)&g_h16[r1 * HID + w * 8 + tig * 2] = *(unsigned*)&p;
    }
}

// ---------------- fused hidden layer: gather + HMMA GEMM (+ optional pool) -----------
// block = 16 nodes, 256 threads
#define SH 72   // Xs stride in halves (64 + 8 pad, conflict-free)
template <bool DO_POOL>
__global__ void k_layerh(const __half* __restrict__ hin, __half* __restrict__ hout,
                         const __half* __restrict__ Wt, const float* __restrict__ b,
                         const void* batch) {
    __shared__ __align__(16) __half Xs[16 * SH];
    __shared__ float Hs[16 * HID];
    int t = threadIdx.x;
    int n0 = blockIdx.x * 16;
    int node = n0 + (t >> 4);
    int c = t & 15;

    float di = (node < NN) ? g_dinv[node] : 0.0f;

    // ---- phase 1: gather with prefetched indices; independent payload chains ----
    {
        float acc[4] = {0, 0, 0, 0};
        if (node < NN) {
            uint2 own = *(const uint2*)&hin[node * HID + c * 4];
            add4_h(own, acc);
            int e0 = node * BKT;
            int e1 = e0 + g_cnt[node];
            int e = e0;
            int s0 = g_esrc[e];              // over-read safe in padded bucket
            int s1 = g_esrc[e + 1];
            for (; e + 1 < e1; e += 2) {
                uint2 u0 = *(const uint2*)&hin[s0 * HID + c * 4];
                uint2 u1 = *(const uint2*)&hin[s1 * HID + c * 4];
                s0 = g_esrc[e + 2];          // prefetch next pair
                s1 = g_esrc[e + 3];
                add4_h(u0, acc);
                add4_h(u1, acc);
            }
            if (e < e1) {                    // s0 == g_esrc[e]
                uint2 u = *(const uint2*)&hin[s0 * HID + c * 4];
                add4_h(u, acc);
            }
        }
        __half2 p0 = __floats2half2_rn(di * acc[0], di * acc[1]);
        __half2 p1 = __floats2half2_rn(di * acc[2], di * acc[3]);
        uint2 pk = make_uint2(*(unsigned*)&p0, *(unsigned*)&p1);
        *(uint2*)&Xs[(t >> 4) * SH + c * 4] = pk;
    }
    __syncthreads();

    // ---- phase 2: HMMA GEMM: warp w -> n-tile w, K=64 (4 ksteps) ----
    int w = t >> 5;
    int lane = t & 31;
    int gid = lane >> 2, tig = lane & 3;
    float2 bb = *(const float2*)&b[w * 8 + tig * 2];
    float d0 = bb.x, d1 = bb.y, d2 = bb.x, d3 = bb.y;
#pragma unroll
    for (int kk = 0; kk < 4; kk++) {
        int ka = kk * 16 + tig * 2;
        unsigned a0 = *(const unsigned*)&Xs[gid * SH + ka];
        unsigned a1 = *(const unsigned*)&Xs[(gid + 8) * SH + ka];
        unsigned a2 = *(const unsigned*)&Xs[gid * SH + ka + 8];
        unsigned a3 = *(const unsigned*)&Xs[(gid + 8) * SH + ka + 8];
        unsigned b0 = *(const unsigned*)&Wt[(w * 8 + gid) * HID + ka];
        unsigned b1 = *(const unsigned*)&Wt[(w * 8 + gid) * HID + ka + 8];
        mma16816(d0, d1, d2, d3, a0, a1, a2, a3, b0, b1);
    }
    d0 = fmaxf(d0, 0.f); d1 = fmaxf(d1, 0.f);
    d2 = fmaxf(d2, 0.f); d3 = fmaxf(d3, 0.f);

    int r0 = n0 + gid, r1 = n0 + gid + 8;
    if (!DO_POOL) {
        if (r0 < NN) {
            float s = g_dinv[r0];
            __half2 p = __floats2half2_rn(s * d0, s * d1);
            *(unsigned*)&hout[r0 * HID + w * 8 + tig * 2] = *(unsigned*)&p;
        }
        if (r1 < NN) {
            float s = g_dinv[r1];
            __half2 p = __floats2half2_rn(s * d2, s * d3);
            *(unsigned*)&hout[r1 * HID + w * 8 + tig * 2] = *(unsigned*)&p;
        }
    } else {
        Hs[gid * HID + w * 8 + tig * 2]       = d0;
        Hs[gid * HID + w * 8 + tig * 2 + 1]   = d1;
        Hs[(gid + 8) * HID + w * 8 + tig * 2]     = d2;
        Hs[(gid + 8) * HID + w * 8 + tig * 2 + 1] = d3;
        __syncthreads();
        // ---- phase 3: segmented pool over this block's 16 nodes ----
        if (t < 16) {
            int lim = NN - n0; if (lim > 16) lim = 16;
            if (lim <= 0) return;
            int is64 = g_i64;
            float4 acc = make_float4(0, 0, 0, 0);
            float cnt = 0.0f;
            int cur = ld_idx(batch, n0, is64);
            for (int i = 0; i < lim; i++) {
                int g = ld_idx(batch, n0 + i, is64);
                if (g != cur) {
                    red_add_v4(&g_sums[cur * HID + t * 4], acc);
                    if (t == 0) atomicAdd(&g_cnts[cur], cnt);
                    acc = make_float4(0, 0, 0, 0);
                    cnt = 0.0f;
                    cur = g;
                }
                float4 v = *(const float4*)&Hs[i * HID + t * 4];
                acc.x += v.x; acc.y += v.y; acc.z += v.z; acc.w += v.w;
                cnt += 1.0f;
            }
            red_add_v4(&g_sums[cur * HID + t * 4], acc);
            if (t == 0) atomicAdd(&g_cnts[cur], cnt);
        }
    }
}

// ---------------- final MLP head ------------------------------------------------------
__global__ void k_mlp(const float* __restrict__ lw1, const float* __restrict__ lb1,
                      const float* __restrict__ lw2, const float* __restrict__ lb2,
                      float* __restrict__ out) {
    int g = blockIdx.x;
    int j = threadIdx.x;  // 64
    __shared__ float gs[HID];
    __shared__ float red[HID];
    float cnt = fmaxf(g_cnts[g], 1.0f);
    gs[j] = g_sums[g * HID + j] / cnt;
    __syncthreads();
    float t = lb1[j];
#pragma unroll
    for (int k = 0; k < HID; k++) t += gs[k] * lw1[k * HID + j];
    t = fmaxf(t, 0.0f);
    red[j] = t * lw2[j];
    __syncthreads();
    for (int s = 32; s > 0; s >>= 1) {
        if (j < s) red[j] += red[j + s];
        __syncthreads();
    }
    if (j == 0) out[g] = red[0] + lb2[0];
}

// ---------------- launch -----------------------------------------------------------------
extern "C" void kernel_launch(void* const* d_in, const int* in_sizes, int n_in,
                              void* d_out, int out_size) {
    const float* x   = (const float*)d_in[0];
    const float* W1  = (const float*)d_in[1];
    const float* b1  = (const float*)d_in[2];
    const float* W2  = (const float*)d_in[3];
    const float* b2  = (const float*)d_in[4];
    const float* W3  = (const float*)d_in[5];
    const float* b3  = (const float*)d_in[6];
    const float* lw1 = (const float*)d_in[7];
    const float* lb1 = (const float*)d_in[8];
    const float* lw2 = (const float*)d_in[9];
    const float* lb2 = (const float*)d_in[10];
    const void*  ei  = d_in[11];
    const void*  bat = d_in[12];

    __half* h16;  cudaGetSymbolAddress((void**)&h16,  g_h16);
    __half* h16b; cudaGetSymbolAddress((void**)&h16b, g_h16b);
    __half* wt2;  cudaGetSymbolAddress((void**)&wt2,  g_wt2);
    __half* wt3;  cudaGetSymbolAddress((void**)&wt3,  g_wt3);

    const int T = 256;
    k_setup<<<(NG * HID + T - 1) / T, T>>>((const unsigned int*)ei, W1, W2, W3);
    k_fillp<<<(NE / 4 + T - 1) / T, T>>>(ei);
    k_x2h<<<(NN * 32 + T - 1) / T, T>>>(x);

    int gNodes16 = (NN + 15) / 16;

    k_layer1<<<gNodes16, T>>>(b1);
    k_layerh<false><<<gNodes16, T>>>(h16, h16b, wt2, b2, bat);
    k_layerh<true><<<gNodes16, T>>>(h16b, h16, wt3, b3, bat);

    k_mlp<<<NG, HID>>>(lw1, lb1, lw2, lb2, (float*)d_out);
}